// round 10
// baseline (speedup 1.0000x reference)
#include <cuda_runtime.h>
#include <cuda_fp16.h>

#define N_NODES 100000
#define N_EDGES 3200000
#define IN_DIM  128
#define HID     64

#define SCAN_B  512
#define SCAN_NB ((N_NODES + SCAN_B - 1) / SCAN_B)   // 196

// ---------------- scratch (device globals; no allocation allowed) ----------------
__device__ int     g_is64;                  // 1 if edge_index is int64, 0 if int32
__device__ int     g_deg[N_NODES];          // incoming-edge COUNT (memset 0 each run)
__device__ float   g_dinv[N_NODES];
__device__ int     g_rowptr[N_NODES + 1];
__device__ int     g_cursor[N_NODES];
__device__ unsigned long long g_tstat[SCAN_NB];   // lookback status (memset 0 each run)
__device__ int     g_csr[N_EDGES];          // src index only
__device__ __half2 g_h1h[N_NODES * (HID/2)];// h1' = dinv * (x @ W1^T), fp16
__device__ float   g_z[N_NODES];            // z'  = dinv * (a1 . w)
__device__ float   g_w[HID];                // w = W2^T @ Wc
__device__ float   g_cb;                    // b2.Wc + bc

// ---------------- prep: dtype probe + classifier fold (2 blocks) ----------------
__global__ void prep_kernel(const unsigned* __restrict__ ei32,
                            const float* __restrict__ W2, const float* __restrict__ b2,
                            const float* __restrict__ Wc, const float* __restrict__ bc) {
    int tid = threadIdx.x;
    if (blockIdx.x == 0) {
        if (tid == 0) {
            // int64 ids in [0,100000) => every odd 32-bit word is 0.
            unsigned o = 0;
            #pragma unroll
            for (int i = 1; i < 128; i += 2) o |= ei32[i];
            g_is64 = (o == 0) ? 1 : 0;
        }
    } else {
        if (tid < HID) {
            float s = 0.f;
            #pragma unroll
            for (int j = 0; j < HID; j++) s = fmaf(Wc[j], W2[j * HID + tid], s);
            g_w[tid] = s;
            if (tid == 0) {
                float c = bc[0];
                #pragma unroll
                for (int j = 0; j < HID; j++) c = fmaf(b2[j], Wc[j], c);
                g_cb = c;
            }
        }
    }
}

__device__ __forceinline__ int edge_at(const void* ei, long long idx) {
    if (g_is64) return (int)((const long long*)ei)[idx];
    return ((const int*)ei)[idx];
}

// ---------------- dst-degree histogram (1 edge/thread: max atomic MLP) ----------------
__global__ void hist_kernel(const void* __restrict__ ei) {
    int e = blockIdx.x * blockDim.x + threadIdx.x;
    if (e < N_EDGES) {
        int d = edge_at(ei, (long long)N_EDGES + e);
        atomicAdd(&g_deg[d], 1);
    }
}

// ---------------- single-pass exclusive scan (decoupled lookback) ----------------
// g_deg holds raw counts; rowptr/cursor = exclusive prefix of counts;
// dinv = rsqrt(count + 1) (self-loop).
__device__ __forceinline__ unsigned long long pack_st(unsigned flag, unsigned sum) {
    return ((unsigned long long)flag << 32) | sum;
}

__global__ void scanlb_kernel() {
    __shared__ int wsum[16];
    __shared__ int s_base;
    const int tid  = threadIdx.x;
    const int lane = tid & 31, warp = tid >> 5;
    const int bid  = blockIdx.x;
    const int i = bid * SCAN_B + tid;

    int cnt = (i < N_NODES) ? g_deg[i] : 0;
    int s = cnt;
    #pragma unroll
    for (int o = 1; o < 32; o <<= 1) {
        int t = __shfl_up_sync(0xffffffffu, s, o);
        if (lane >= o) s += t;
    }
    if (lane == 31) wsum[warp] = s;
    __syncthreads();
    if (warp == 0) {
        int ws = (lane < 16) ? wsum[lane] : 0;
        #pragma unroll
        for (int o = 1; o < 16; o <<= 1) {
            int t = __shfl_up_sync(0xffffffffu, ws, o);
            if (lane >= o) ws += t;
        }
        if (lane < 16) wsum[lane] = ws;
    }
    __syncthreads();
    int excl  = s - cnt + (warp ? wsum[warp - 1] : 0);   // block-local exclusive
    int total = wsum[15];                                 // block aggregate

    if (tid == 0) {
        if (bid == 0) {
            __threadfence();
            atomicExch(&g_tstat[0], pack_st(2u, (unsigned)total));
            s_base = 0;
        } else {
            __threadfence();
            atomicExch(&g_tstat[bid], pack_st(1u, (unsigned)total));   // aggregate
            // lookback
            unsigned run = 0;
            int j = bid - 1;
            while (true) {
                unsigned long long st = atomicAdd(&g_tstat[j], 0ULL);
                unsigned flag = (unsigned)(st >> 32);
                if (flag == 2u) { run += (unsigned)st; break; }
                if (flag == 1u) { run += (unsigned)st; j--; }
                else __nanosleep(40);
            }
            s_base = (int)run;
            __threadfence();
            atomicExch(&g_tstat[bid], pack_st(2u, run + (unsigned)total));  // inclusive prefix
        }
    }
    __syncthreads();

    int off = s_base + excl;
    if (i < N_NODES) {
        g_rowptr[i] = off;
        g_cursor[i] = off;
        g_dinv[i]   = rsqrtf((float)(cnt + 1));
    }
    if (i == 0) g_rowptr[N_NODES] = N_EDGES;   // sum(counts) == E
}

// ---------------- counting-sort scatter (1 edge/thread: max atomic MLP) ----------------
__global__ void scatter_kernel(const void* __restrict__ ei) {
    int e = blockIdx.x * blockDim.x + threadIdx.x;
    if (e < N_EDGES) {
        int s = edge_at(ei, e);
        int d = edge_at(ei, (long long)N_EDGES + e);
        int pos = atomicAdd(&g_cursor[d], 1);
        g_csr[pos] = s;
    }
}

// ---------------- tf32 helpers ----------------
__device__ __forceinline__ unsigned f2tf(float f) {
    unsigned u;
    asm("cvt.rna.tf32.f32 %0, %1;" : "=r"(u) : "f"(f));
    return u;
}

__device__ __forceinline__ void mma_tf32(float* c,
                                         unsigned a0, unsigned a1, unsigned a2, unsigned a3,
                                         unsigned b0, unsigned b1) {
    asm volatile(
        "mma.sync.aligned.m16n8k8.row.col.f32.tf32.tf32.f32 "
        "{%0,%1,%2,%3},{%4,%5,%6,%7},{%8,%9},{%0,%1,%2,%3};"
        : "+f"(c[0]), "+f"(c[1]), "+f"(c[2]), "+f"(c[3])
        : "r"(a0), "r"(a1), "r"(a2), "r"(a3), "r"(b0), "r"(b1));
}

// ---------------- GEMM1 (tensor core, tf32): h1' = fp16(dinv * (x @ W1^T)) ----------------
#define GPAD 68
__global__ void gemm1_kernel(const float* __restrict__ X, const float* __restrict__ W) {
    __shared__ unsigned As[64 * GPAD];   // A tile (tf32 bits), [node_local][k]
    __shared__ unsigned Ws[64 * GPAD];   // W tile (tf32 bits), [out_ch][k]

    const int tid  = threadIdx.x;
    const int warp = tid >> 5, lane = tid & 31;
    const int g    = lane >> 2, tig = lane & 3;
    const int m0   = (warp >> 1) * 16;
    const int nb   = (warp & 1) * 32;
    const int node0 = blockIdx.x * 64;

    float c[4][4];
    #pragma unroll
    for (int nt = 0; nt < 4; nt++)
        #pragma unroll
        for (int j = 0; j < 4; j++) c[nt][j] = 0.f;

    #pragma unroll
    for (int kt = 0; kt < IN_DIM; kt += 64) {
        #pragma unroll
        for (int i = tid; i < 64 * 64; i += 256) {
            int r = i >> 6, k = i & 63;
            int node = node0 + r;
            if (node > N_NODES - 1) node = N_NODES - 1;
            As[r * GPAD + k] = f2tf(X[node * IN_DIM + kt + k]);
        }
        #pragma unroll
        for (int i = tid; i < 64 * 64; i += 256) {
            int r = i >> 6, k = i & 63;
            Ws[r * GPAD + k] = f2tf(W[r * IN_DIM + kt + k]);
        }
        __syncthreads();

        #pragma unroll
        for (int ks = 0; ks < 8; ks++) {
            int k0 = ks * 8;
            unsigned a0 = As[(m0 + g)     * GPAD + k0 + tig];
            unsigned a1 = As[(m0 + g + 8) * GPAD + k0 + tig];
            unsigned a2 = As[(m0 + g)     * GPAD + k0 + tig + 4];
            unsigned a3 = As[(m0 + g + 8) * GPAD + k0 + tig + 4];
            #pragma unroll
            for (int nt = 0; nt < 4; nt++) {
                int n0 = nb + nt * 8;
                unsigned b0 = Ws[(n0 + g) * GPAD + k0 + tig];
                unsigned b1 = Ws[(n0 + g) * GPAD + k0 + tig + 4];
                mma_tf32(c[nt], a0, a1, a2, a3, b0, b1);
            }
        }
        __syncthreads();
    }

    int nodeA = node0 + m0 + g;
    int nodeB = nodeA + 8;
    int colh  = (nb >> 1) + tig;
    if (nodeA < N_NODES) {
        float di = g_dinv[nodeA];
        #pragma unroll
        for (int nt = 0; nt < 4; nt++)
            g_h1h[nodeA * 32 + colh + nt * 4] = __floats2half2_rn(c[nt][0] * di, c[nt][1] * di);
    }
    if (nodeB < N_NODES) {
        float di = g_dinv[nodeB];
        #pragma unroll
        for (int nt = 0; nt < 4; nt++)
            g_h1h[nodeB * 32 + colh + nt * 4] = __floats2half2_rn(c[nt][2] * di, c[nt][3] * di);
    }
}

// ---------------- agg1: 4 edges per warp-instruction, fused layer-2 fold ----------------
__global__ void agg1_kernel(const float* __restrict__ b1) {
    int warp = threadIdx.x >> 5, lane = threadIdx.x & 31;
    int node = blockIdx.x * 8 + warp;
    if (node >= N_NODES) return;

    const int g = lane >> 3, c = lane & 7;
    const uint4* __restrict__ h4 = (const uint4*)g_h1h;   // 8 channels per uint4

    int rbeg = g_rowptr[node];
    int rend = g_rowptr[node + 1];

    float acc[8];
    #pragma unroll
    for (int j = 0; j < 8; j++) acc[j] = 0.f;

    for (int eb = rbeg; eb < rend; eb += 4) {
        int e = eb + g;
        if (e < rend) {
            int s = g_csr[e];
            uint4 v = h4[s * 8 + c];
            const __half2* hp = (const __half2*)&v;
            #pragma unroll
            for (int j = 0; j < 4; j++) {
                float2 f = __half22float2(hp[j]);
                acc[2 * j]     += f.x;
                acc[2 * j + 1] += f.y;
            }
        }
    }
    #pragma unroll
    for (int j = 0; j < 8; j++) {
        acc[j] += __shfl_xor_sync(0xffffffffu, acc[j], 8);
        acc[j] += __shfl_xor_sync(0xffffffffu, acc[j], 16);
    }
    {
        uint4 v = h4[node * 8 + c];
        const __half2* hp = (const __half2*)&v;
        #pragma unroll
        for (int j = 0; j < 4; j++) {
            float2 f = __half22float2(hp[j]);
            acc[2 * j]     += f.x;
            acc[2 * j + 1] += f.y;
        }
    }

    float di = g_dinv[node];
    float4 bb0 = ((const float4*)b1)[c * 2];
    float4 bb1 = ((const float4*)b1)[c * 2 + 1];
    float4 wv0 = ((const float4*)g_w)[c * 2];
    float4 wv1 = ((const float4*)g_w)[c * 2 + 1];
    float bb[8] = {bb0.x, bb0.y, bb0.z, bb0.w, bb1.x, bb1.y, bb1.z, bb1.w};
    float wv[8] = {wv0.x, wv0.y, wv0.z, wv0.w, wv1.x, wv1.y, wv1.z, wv1.w};

    float p = 0.f;
    #pragma unroll
    for (int j = 0; j < 8; j++) {
        float a = fmaxf(fmaf(di, acc[j], bb[j]), 0.f);
        p = fmaf(a, wv[j], p);
    }
    p += __shfl_xor_sync(0xffffffffu, p, 1);
    p += __shfl_xor_sync(0xffffffffu, p, 2);
    p += __shfl_xor_sync(0xffffffffu, p, 4);
    if (lane == 0) g_z[node] = di * p;           // z' = dinv * (a1 . w)
}

// ---------------- agg2 (scalar): out[d] = dinv_d*(sum_s z'[s] + z'[d]) + cb ----------------
__global__ void agg2_kernel(float* __restrict__ out) {
    int warp = threadIdx.x >> 5, lane = threadIdx.x & 31;
    int node = blockIdx.x * 8 + warp;
    if (node >= N_NODES) return;

    int rbeg = g_rowptr[node];
    int rend = g_rowptr[node + 1];
    float acc = 0.f;
    for (int e = rbeg + lane; e < rend; e += 32) {
        acc += g_z[g_csr[e]];
    }
    #pragma unroll
    for (int o = 16; o > 0; o >>= 1) acc += __shfl_xor_sync(0xffffffffu, acc, o);
    if (lane == 0) out[node] = g_dinv[node] * (acc + g_z[node]) + g_cb;
}

// ---------------- launch (serial single stream) ----------------
extern "C" void kernel_launch(void* const* d_in, const int* in_sizes, int n_in,
                              void* d_out, int out_size) {
    const float* x  = (const float*)d_in[0];
    const void*  ei = d_in[1];                 // int32 or int64, probed on device
    const float* W1 = (const float*)d_in[2];
    const float* b1 = (const float*)d_in[3];
    const float* W2 = (const float*)d_in[4];
    const float* b2 = (const float*)d_in[5];
    const float* Wc = (const float*)d_in[6];
    const float* bc = (const float*)d_in[7];
    float* out = (float*)d_out;

    // reset count + lookback-status arrays (graph-capturable memset nodes)
    void* p_deg = nullptr;  cudaGetSymbolAddress(&p_deg, g_deg);
    void* p_st  = nullptr;  cudaGetSymbolAddress(&p_st,  g_tstat);
    cudaMemsetAsync(p_deg, 0, N_NODES * sizeof(int), 0);
    cudaMemsetAsync(p_st,  0, SCAN_NB * sizeof(unsigned long long), 0);

    prep_kernel   <<<2, 256>>>((const unsigned*)ei, W2, b2, Wc, bc);
    hist_kernel   <<<N_EDGES / 256, 256>>>(ei);
    scanlb_kernel <<<SCAN_NB, SCAN_B>>>();
    scatter_kernel<<<N_EDGES / 256, 256>>>(ei);
    gemm1_kernel  <<<(N_NODES + 63) / 64, 256>>>(x, W1);
    agg1_kernel   <<<(N_NODES + 7) / 8, 256>>>(b1);
    agg2_kernel   <<<(N_NODES + 7) / 8, 256>>>(out);
}

// round 11
// speedup vs baseline: 1.0657x; 1.0657x over previous
#include <cuda_runtime.h>
#include <cuda_fp16.h>

#define N_NODES 100000
#define N_EDGES 3200000
#define IN_DIM  128
#define HID     64

#define SCAN_B  512
#define SCAN_NB ((N_NODES + SCAN_B - 1) / SCAN_B)   // 196
#define PREP_NB ((N_NODES + 255) / 256)             // 391

// ---------------- scratch (device globals; no allocation allowed) ----------------
__device__ int     g_is64;                  // 1 if edge_index is int64, 0 if int32
__device__ int     g_deg[N_NODES];
__device__ float   g_dinv[N_NODES];
__device__ int     g_rowptr[N_NODES + 1];
__device__ int     g_cursor[N_NODES];
__device__ int     g_scan[N_NODES];
__device__ int     g_bsum[SCAN_NB];
__device__ int     g_boff[SCAN_NB];
__device__ int     g_csr[N_EDGES];          // src index only
__device__ __half2 g_h1h[N_NODES * (HID/2)];// h1' = dinv * (x @ W1^T), fp16
__device__ float   g_z[N_NODES];            // z'  = dinv * (a1 . w)
__device__ float   g_w[HID];                // w = W2^T @ Wc
__device__ float   g_cb;                    // b2.Wc + bc

// ---------------- prep: deg init + dtype probe + classifier fold (one launch) ----------------
__global__ void prep_kernel(const unsigned* __restrict__ ei32,
                            const float* __restrict__ W2, const float* __restrict__ b2,
                            const float* __restrict__ Wc, const float* __restrict__ bc) {
    int b = blockIdx.x, tid = threadIdx.x;
    if (b < PREP_NB) {
        int i = b * 256 + tid;
        if (i < N_NODES) g_deg[i] = 1;          // self-loop counts as 1
    } else if (b == PREP_NB) {
        if (tid == 0) {
            // int64 ids in [0,100000) => every odd 32-bit word is 0.
            unsigned o = 0;
            #pragma unroll
            for (int i = 1; i < 128; i += 2) o |= ei32[i];
            g_is64 = (o == 0) ? 1 : 0;
        }
    } else {
        if (tid < HID) {
            float s = 0.f;
            #pragma unroll
            for (int j = 0; j < HID; j++) s = fmaf(Wc[j], W2[j * HID + tid], s);
            g_w[tid] = s;
            if (tid == 0) {
                float c = bc[0];
                #pragma unroll
                for (int j = 0; j < HID; j++) c = fmaf(b2[j], Wc[j], c);
                g_cb = c;
            }
        }
    }
}

__device__ __forceinline__ int edge_at(const void* ei, long long idx) {
    if (g_is64) return (int)((const long long*)ei)[idx];
    return ((const int*)ei)[idx];
}

// ---------------- dst-degree histogram (1 edge/thread: max atomic MLP) ----------------
__global__ void hist_kernel(const void* __restrict__ ei) {
    int e = blockIdx.x * blockDim.x + threadIdx.x;
    if (e < N_EDGES) {
        int d = edge_at(ei, (long long)N_EDGES + e);
        atomicAdd(&g_deg[d], 1);
    }
}

// ---------------- parallel 3-phase exclusive scan of (deg-1) ----------------
__global__ void scan1_kernel() {
    __shared__ int wsum[16];
    const int tid  = threadIdx.x;
    const int lane = tid & 31, warp = tid >> 5;
    const int i = blockIdx.x * SCAN_B + tid;
    int v = (i < N_NODES) ? (g_deg[i] - 1) : 0;
    int s = v;
    #pragma unroll
    for (int o = 1; o < 32; o <<= 1) {
        int t = __shfl_up_sync(0xffffffffu, s, o);
        if (lane >= o) s += t;
    }
    if (lane == 31) wsum[warp] = s;
    __syncthreads();
    if (warp == 0) {
        int ws = (lane < 16) ? wsum[lane] : 0;
        #pragma unroll
        for (int o = 1; o < 16; o <<= 1) {
            int t = __shfl_up_sync(0xffffffffu, ws, o);
            if (lane >= o) ws += t;
        }
        if (lane < 16) wsum[lane] = ws;
    }
    __syncthreads();
    int excl = s - v + (warp ? wsum[warp - 1] : 0);
    if (i < N_NODES) g_scan[i] = excl;
    if (tid == SCAN_B - 1) g_bsum[blockIdx.x] = excl + v;
}

__global__ void scan2_kernel() {       // 1 block, 256 threads (>=196)
    __shared__ int sh[256];
    const int t = threadIdx.x;
    int v0 = (t < SCAN_NB) ? g_bsum[t] : 0;
    sh[t] = v0;
    __syncthreads();
    #pragma unroll
    for (int o = 1; o < 256; o <<= 1) {
        int v = (t >= o) ? sh[t - o] : 0;
        __syncthreads();
        sh[t] += v;
        __syncthreads();
    }
    if (t < SCAN_NB) g_boff[t] = sh[t] - v0;
}

__global__ void scan3_kernel() {
    int i = blockIdx.x * blockDim.x + threadIdx.x;
    if (i < N_NODES) {
        int off = g_scan[i] + g_boff[i / SCAN_B];
        g_rowptr[i] = off;
        g_cursor[i] = off;
        g_dinv[i]   = rsqrtf((float)g_deg[i]);
    }
    if (i == 0) g_rowptr[N_NODES] = N_EDGES;   // sum(deg-1) == E
}

// ---------------- counting-sort scatter (1 edge/thread: max atomic MLP) ----------------
__global__ void scatter_kernel(const void* __restrict__ ei) {
    int e = blockIdx.x * blockDim.x + threadIdx.x;
    if (e < N_EDGES) {
        int s = edge_at(ei, e);
        int d = edge_at(ei, (long long)N_EDGES + e);
        int pos = atomicAdd(&g_cursor[d], 1);
        g_csr[pos] = s;
    }
}

// ---------------- tf32 helpers ----------------
__device__ __forceinline__ unsigned f2tf(float f) {
    unsigned u;
    asm("cvt.rna.tf32.f32 %0, %1;" : "=r"(u) : "f"(f));
    return u;
}

__device__ __forceinline__ void mma_tf32(float* c,
                                         unsigned a0, unsigned a1, unsigned a2, unsigned a3,
                                         unsigned b0, unsigned b1) {
    asm volatile(
        "mma.sync.aligned.m16n8k8.row.col.f32.tf32.tf32.f32 "
        "{%0,%1,%2,%3},{%4,%5,%6,%7},{%8,%9},{%0,%1,%2,%3};"
        : "+f"(c[0]), "+f"(c[1]), "+f"(c[2]), "+f"(c[3])
        : "r"(a0), "r"(a1), "r"(a2), "r"(a3), "r"(b0), "r"(b1));
}

// ---------------- GEMM1 (tensor core, tf32): h1' = fp16(dinv * (x @ W1^T)) ----------------
#define GPAD 68
__global__ void gemm1_kernel(const float* __restrict__ X, const float* __restrict__ W) {
    __shared__ unsigned As[64 * GPAD];   // A tile (tf32 bits), [node_local][k]
    __shared__ unsigned Ws[64 * GPAD];   // W tile (tf32 bits), [out_ch][k]

    const int tid  = threadIdx.x;
    const int warp = tid >> 5, lane = tid & 31;
    const int g    = lane >> 2, tig = lane & 3;
    const int m0   = (warp >> 1) * 16;
    const int nb   = (warp & 1) * 32;
    const int node0 = blockIdx.x * 64;

    float c[4][4];
    #pragma unroll
    for (int nt = 0; nt < 4; nt++)
        #pragma unroll
        for (int j = 0; j < 4; j++) c[nt][j] = 0.f;

    #pragma unroll
    for (int kt = 0; kt < IN_DIM; kt += 64) {
        #pragma unroll
        for (int i = tid; i < 64 * 64; i += 256) {
            int r = i >> 6, k = i & 63;
            int node = node0 + r;
            if (node > N_NODES - 1) node = N_NODES - 1;
            As[r * GPAD + k] = f2tf(X[node * IN_DIM + kt + k]);
        }
        #pragma unroll
        for (int i = tid; i < 64 * 64; i += 256) {
            int r = i >> 6, k = i & 63;
            Ws[r * GPAD + k] = f2tf(W[r * IN_DIM + kt + k]);
        }
        __syncthreads();

        #pragma unroll
        for (int ks = 0; ks < 8; ks++) {
            int k0 = ks * 8;
            unsigned a0 = As[(m0 + g)     * GPAD + k0 + tig];
            unsigned a1 = As[(m0 + g + 8) * GPAD + k0 + tig];
            unsigned a2 = As[(m0 + g)     * GPAD + k0 + tig + 4];
            unsigned a3 = As[(m0 + g + 8) * GPAD + k0 + tig + 4];
            #pragma unroll
            for (int nt = 0; nt < 4; nt++) {
                int n0 = nb + nt * 8;
                unsigned b0 = Ws[(n0 + g) * GPAD + k0 + tig];
                unsigned b1 = Ws[(n0 + g) * GPAD + k0 + tig + 4];
                mma_tf32(c[nt], a0, a1, a2, a3, b0, b1);
            }
        }
        __syncthreads();
    }

    int nodeA = node0 + m0 + g;
    int nodeB = nodeA + 8;
    int colh  = (nb >> 1) + tig;
    if (nodeA < N_NODES) {
        float di = g_dinv[nodeA];
        #pragma unroll
        for (int nt = 0; nt < 4; nt++)
            g_h1h[nodeA * 32 + colh + nt * 4] = __floats2half2_rn(c[nt][0] * di, c[nt][1] * di);
    }
    if (nodeB < N_NODES) {
        float di = g_dinv[nodeB];
        #pragma unroll
        for (int nt = 0; nt < 4; nt++)
            g_h1h[nodeB * 32 + colh + nt * 4] = __floats2half2_rn(c[nt][2] * di, c[nt][3] * di);
    }
}

// ---------------- agg1: 8 edges per iteration (2 gathers in flight), fused fold ----------------
__global__ void agg1_kernel(const float* __restrict__ b1) {
    int warp = threadIdx.x >> 5, lane = threadIdx.x & 31;
    int node = blockIdx.x * 8 + warp;
    if (node >= N_NODES) return;

    const int g = lane >> 3, c = lane & 7;
    const uint4* __restrict__ h4 = (const uint4*)g_h1h;   // 8 channels per uint4

    int rbeg = g_rowptr[node];
    int rend = g_rowptr[node + 1];

    float acc[8];
    #pragma unroll
    for (int j = 0; j < 8; j++) acc[j] = 0.f;

    int eb = rbeg;
    // main body: 8 edges per iteration, no per-edge branch, 2 independent gathers
    for (; eb + 8 <= rend; eb += 8) {
        int s0 = g_csr[eb + g];
        int s1 = g_csr[eb + 4 + g];
        uint4 v0 = h4[s0 * 8 + c];
        uint4 v1 = h4[s1 * 8 + c];
        const __half2* hp0 = (const __half2*)&v0;
        const __half2* hp1 = (const __half2*)&v1;
        #pragma unroll
        for (int j = 0; j < 4; j++) {
            float2 f0 = __half22float2(hp0[j]);
            float2 f1 = __half22float2(hp1[j]);
            acc[2 * j]     += f0.x + f1.x;
            acc[2 * j + 1] += f0.y + f1.y;
        }
    }
    // tail: guarded quads
    for (; eb < rend; eb += 4) {
        int e = eb + g;
        if (e < rend) {
            int s = g_csr[e];
            uint4 v = h4[s * 8 + c];
            const __half2* hp = (const __half2*)&v;
            #pragma unroll
            for (int j = 0; j < 4; j++) {
                float2 f = __half22float2(hp[j]);
                acc[2 * j]     += f.x;
                acc[2 * j + 1] += f.y;
            }
        }
    }
    #pragma unroll
    for (int j = 0; j < 8; j++) {
        acc[j] += __shfl_xor_sync(0xffffffffu, acc[j], 8);
        acc[j] += __shfl_xor_sync(0xffffffffu, acc[j], 16);
    }
    {   // self term (h1' already dinv-scaled)
        uint4 v = h4[node * 8 + c];
        const __half2* hp = (const __half2*)&v;
        #pragma unroll
        for (int j = 0; j < 4; j++) {
            float2 f = __half22float2(hp[j]);
            acc[2 * j]     += f.x;
            acc[2 * j + 1] += f.y;
        }
    }

    float di = g_dinv[node];
    float4 bb0 = ((const float4*)b1)[c * 2];
    float4 bb1 = ((const float4*)b1)[c * 2 + 1];
    float4 wv0 = ((const float4*)g_w)[c * 2];
    float4 wv1 = ((const float4*)g_w)[c * 2 + 1];
    float bb[8] = {bb0.x, bb0.y, bb0.z, bb0.w, bb1.x, bb1.y, bb1.z, bb1.w};
    float wv[8] = {wv0.x, wv0.y, wv0.z, wv0.w, wv1.x, wv1.y, wv1.z, wv1.w};

    float p = 0.f;
    #pragma unroll
    for (int j = 0; j < 8; j++) {
        float a = fmaxf(fmaf(di, acc[j], bb[j]), 0.f);
        p = fmaf(a, wv[j], p);
    }
    p += __shfl_xor_sync(0xffffffffu, p, 1);
    p += __shfl_xor_sync(0xffffffffu, p, 2);
    p += __shfl_xor_sync(0xffffffffu, p, 4);
    if (lane == 0) g_z[node] = di * p;           // z' = dinv * (a1 . w)
}

// ---------------- agg2 (scalar): out[d] = dinv_d*(sum_s z'[s] + z'[d]) + cb ----------------
__global__ void agg2_kernel(float* __restrict__ out) {
    int warp = threadIdx.x >> 5, lane = threadIdx.x & 31;
    int node = blockIdx.x * 8 + warp;
    if (node >= N_NODES) return;

    int rbeg = g_rowptr[node];
    int rend = g_rowptr[node + 1];
    float acc = 0.f;
    for (int e = rbeg + lane; e < rend; e += 32) {
        acc += g_z[g_csr[e]];
    }
    #pragma unroll
    for (int o = 16; o > 0; o >>= 1) acc += __shfl_xor_sync(0xffffffffu, acc, o);
    if (lane == 0) out[node] = g_dinv[node] * (acc + g_z[node]) + g_cb;
}

// ---------------- launch (serial single stream) ----------------
extern "C" void kernel_launch(void* const* d_in, const int* in_sizes, int n_in,
                              void* d_out, int out_size) {
    const float* x  = (const float*)d_in[0];
    const void*  ei = d_in[1];                 // int32 or int64, probed on device
    const float* W1 = (const float*)d_in[2];
    const float* b1 = (const float*)d_in[3];
    const float* W2 = (const float*)d_in[4];
    const float* b2 = (const float*)d_in[5];
    const float* Wc = (const float*)d_in[6];
    const float* bc = (const float*)d_in[7];
    float* out = (float*)d_out;

    prep_kernel   <<<PREP_NB + 2, 256>>>((const unsigned*)ei, W2, b2, Wc, bc);
    hist_kernel   <<<N_EDGES / 256, 256>>>(ei);
    scan1_kernel  <<<SCAN_NB, SCAN_B>>>();
    scan2_kernel  <<<1, 256>>>();
    scan3_kernel  <<<(N_NODES + 511) / 512, 512>>>();
    scatter_kernel<<<N_EDGES / 256, 256>>>(ei);
    gemm1_kernel  <<<(N_NODES + 63) / 64, 256>>>(x, W1);
    agg1_kernel   <<<(N_NODES + 7) / 8, 256>>>(b1);
    agg2_kernel   <<<(N_NODES + 7) / 8, 256>>>(out);
}

// round 12
// speedup vs baseline: 1.1058x; 1.0377x over previous
#include <cuda_runtime.h>
#include <cuda_fp16.h>

#define N_NODES 100000
#define N_EDGES 3200000
#define IN_DIM  128
#define HID     64

#define SCAN_B  512
#define SCAN_NB ((N_NODES + SCAN_B - 1) / SCAN_B)   // 196
#define PREP_NB ((N_NODES + 255) / 256)             // 391

// ---------------- scratch (device globals; no allocation allowed) ----------------
__device__ int     g_is64;                  // 1 if edge_index is int64, 0 if int32
__device__ int     g_deg[N_NODES];
__device__ float   g_dinv[N_NODES];
__device__ int     g_rowptr[N_NODES + 1];
__device__ int     g_cursor[N_NODES];
__device__ int     g_scan[N_NODES];
__device__ int     g_bsum[SCAN_NB];
__device__ int     g_boff[SCAN_NB];
__device__ int     g_csr[N_EDGES];          // src index only
__device__ __half2 g_h1h[N_NODES * (HID/2)];// h1' = dinv * (x @ W1^T), fp16
__device__ float   g_z[N_NODES];            // z'  = dinv * (a1 . w)
__device__ float   g_w[HID];                // w = W2^T @ Wc
__device__ float   g_cb;                    // b2.Wc + bc

// ---------------- prep: deg init + dtype probe + classifier fold (one launch) ----------------
__global__ void prep_kernel(const unsigned* __restrict__ ei32,
                            const float* __restrict__ W2, const float* __restrict__ b2,
                            const float* __restrict__ Wc, const float* __restrict__ bc) {
    int b = blockIdx.x, tid = threadIdx.x;
    if (b < PREP_NB) {
        int i = b * 256 + tid;
        if (i < N_NODES) g_deg[i] = 1;          // self-loop counts as 1
    } else if (b == PREP_NB) {
        if (tid == 0) {
            // int64 ids in [0,100000) => every odd 32-bit word is 0.
            unsigned o = 0;
            #pragma unroll
            for (int i = 1; i < 128; i += 2) o |= ei32[i];
            g_is64 = (o == 0) ? 1 : 0;
        }
    } else {
        if (tid < HID) {
            float s = 0.f;
            #pragma unroll
            for (int j = 0; j < HID; j++) s = fmaf(Wc[j], W2[j * HID + tid], s);
            g_w[tid] = s;
            if (tid == 0) {
                float c = bc[0];
                #pragma unroll
                for (int j = 0; j < HID; j++) c = fmaf(b2[j], Wc[j], c);
                g_cb = c;
            }
        }
    }
}

__device__ __forceinline__ int edge_at(const void* ei, long long idx) {
    if (g_is64) return (int)((const long long*)ei)[idx];
    return ((const int*)ei)[idx];
}

// ---------------- dst-degree histogram (1 edge/thread: max atomic MLP) ----------------
__global__ void hist_kernel(const void* __restrict__ ei) {
    int e = blockIdx.x * blockDim.x + threadIdx.x;
    if (e < N_EDGES) {
        int d = edge_at(ei, (long long)N_EDGES + e);
        atomicAdd(&g_deg[d], 1);
    }
}

// ---------------- parallel 3-phase exclusive scan of (deg-1) ----------------
__global__ void scan1_kernel() {
    __shared__ int wsum[16];
    const int tid  = threadIdx.x;
    const int lane = tid & 31, warp = tid >> 5;
    const int i = blockIdx.x * SCAN_B + tid;
    int v = (i < N_NODES) ? (g_deg[i] - 1) : 0;
    int s = v;
    #pragma unroll
    for (int o = 1; o < 32; o <<= 1) {
        int t = __shfl_up_sync(0xffffffffu, s, o);
        if (lane >= o) s += t;
    }
    if (lane == 31) wsum[warp] = s;
    __syncthreads();
    if (warp == 0) {
        int ws = (lane < 16) ? wsum[lane] : 0;
        #pragma unroll
        for (int o = 1; o < 16; o <<= 1) {
            int t = __shfl_up_sync(0xffffffffu, ws, o);
            if (lane >= o) ws += t;
        }
        if (lane < 16) wsum[lane] = ws;
    }
    __syncthreads();
    int excl = s - v + (warp ? wsum[warp - 1] : 0);
    if (i < N_NODES) g_scan[i] = excl;
    if (tid == SCAN_B - 1) g_bsum[blockIdx.x] = excl + v;
}

__global__ void scan2_kernel() {       // 1 block, 256 threads (>=196)
    __shared__ int sh[256];
    const int t = threadIdx.x;
    int v0 = (t < SCAN_NB) ? g_bsum[t] : 0;
    sh[t] = v0;
    __syncthreads();
    #pragma unroll
    for (int o = 1; o < 256; o <<= 1) {
        int v = (t >= o) ? sh[t - o] : 0;
        __syncthreads();
        sh[t] += v;
        __syncthreads();
    }
    if (t < SCAN_NB) g_boff[t] = sh[t] - v0;
}

__global__ void scan3_kernel() {
    int i = blockIdx.x * blockDim.x + threadIdx.x;
    if (i < N_NODES) {
        int off = g_scan[i] + g_boff[i / SCAN_B];
        g_rowptr[i] = off;
        g_cursor[i] = off;
        g_dinv[i]   = rsqrtf((float)g_deg[i]);
    }
    if (i == 0) g_rowptr[N_NODES] = N_EDGES;   // sum(deg-1) == E
}

// ---------------- counting-sort scatter (1 edge/thread: max atomic MLP) ----------------
__global__ void scatter_kernel(const void* __restrict__ ei) {
    int e = blockIdx.x * blockDim.x + threadIdx.x;
    if (e < N_EDGES) {
        int s = edge_at(ei, e);
        int d = edge_at(ei, (long long)N_EDGES + e);
        int pos = atomicAdd(&g_cursor[d], 1);
        g_csr[pos] = s;
    }
}

// ---------------- tf32 helpers ----------------
__device__ __forceinline__ unsigned f2tf(float f) {
    unsigned u;
    asm("cvt.rna.tf32.f32 %0, %1;" : "=r"(u) : "f"(f));
    return u;
}

__device__ __forceinline__ void mma_tf32(float* c,
                                         unsigned a0, unsigned a1, unsigned a2, unsigned a3,
                                         unsigned b0, unsigned b1) {
    asm volatile(
        "mma.sync.aligned.m16n8k8.row.col.f32.tf32.tf32.f32 "
        "{%0,%1,%2,%3},{%4,%5,%6,%7},{%8,%9},{%0,%1,%2,%3};"
        : "+f"(c[0]), "+f"(c[1]), "+f"(c[2]), "+f"(c[3])
        : "r"(a0), "r"(a1), "r"(a2), "r"(a3), "r"(b0), "r"(b1));
}

// ---------------- GEMM1 (tensor core, tf32): h1' = fp16(dinv * (x @ W1^T)) ----------------
#define GPAD 68
__global__ void gemm1_kernel(const float* __restrict__ X, const float* __restrict__ W) {
    __shared__ unsigned As[64 * GPAD];   // A tile (tf32 bits), [node_local][k]
    __shared__ unsigned Ws[64 * GPAD];   // W tile (tf32 bits), [out_ch][k]

    const int tid  = threadIdx.x;
    const int warp = tid >> 5, lane = tid & 31;
    const int g    = lane >> 2, tig = lane & 3;
    const int m0   = (warp >> 1) * 16;
    const int nb   = (warp & 1) * 32;
    const int node0 = blockIdx.x * 64;

    float c[4][4];
    #pragma unroll
    for (int nt = 0; nt < 4; nt++)
        #pragma unroll
        for (int j = 0; j < 4; j++) c[nt][j] = 0.f;

    #pragma unroll
    for (int kt = 0; kt < IN_DIM; kt += 64) {
        #pragma unroll
        for (int i = tid; i < 64 * 64; i += 256) {
            int r = i >> 6, k = i & 63;
            int node = node0 + r;
            if (node > N_NODES - 1) node = N_NODES - 1;
            As[r * GPAD + k] = f2tf(X[node * IN_DIM + kt + k]);
        }
        #pragma unroll
        for (int i = tid; i < 64 * 64; i += 256) {
            int r = i >> 6, k = i & 63;
            Ws[r * GPAD + k] = f2tf(W[r * IN_DIM + kt + k]);
        }
        __syncthreads();

        #pragma unroll
        for (int ks = 0; ks < 8; ks++) {
            int k0 = ks * 8;
            unsigned a0 = As[(m0 + g)     * GPAD + k0 + tig];
            unsigned a1 = As[(m0 + g + 8) * GPAD + k0 + tig];
            unsigned a2 = As[(m0 + g)     * GPAD + k0 + tig + 4];
            unsigned a3 = As[(m0 + g + 8) * GPAD + k0 + tig + 4];
            #pragma unroll
            for (int nt = 0; nt < 4; nt++) {
                int n0 = nb + nt * 8;
                unsigned b0 = Ws[(n0 + g) * GPAD + k0 + tig];
                unsigned b1 = Ws[(n0 + g) * GPAD + k0 + tig + 4];
                mma_tf32(c[nt], a0, a1, a2, a3, b0, b1);
            }
        }
        __syncthreads();
    }

    int nodeA = node0 + m0 + g;
    int nodeB = nodeA + 8;
    int colh  = (nb >> 1) + tig;
    if (nodeA < N_NODES) {
        float di = g_dinv[nodeA];
        #pragma unroll
        for (int nt = 0; nt < 4; nt++)
            g_h1h[nodeA * 32 + colh + nt * 4] = __floats2half2_rn(c[nt][0] * di, c[nt][1] * di);
    }
    if (nodeB < N_NODES) {
        float di = g_dinv[nodeB];
        #pragma unroll
        for (int nt = 0; nt < 4; nt++)
            g_h1h[nodeB * 32 + colh + nt * 4] = __floats2half2_rn(c[nt][2] * di, c[nt][3] * di);
    }
}

// ---------------- agg1: 8 edges per iteration (2 gathers in flight), fused fold ----------------
__global__ void agg1_kernel(const float* __restrict__ b1) {
    int warp = threadIdx.x >> 5, lane = threadIdx.x & 31;
    int node = blockIdx.x * 8 + warp;
    if (node >= N_NODES) return;

    const int g = lane >> 3, c = lane & 7;
    const uint4* __restrict__ h4 = (const uint4*)g_h1h;   // 8 channels per uint4

    int rbeg = g_rowptr[node];
    int rend = g_rowptr[node + 1];

    float acc[8];
    #pragma unroll
    for (int j = 0; j < 8; j++) acc[j] = 0.f;

    int eb = rbeg;
    for (; eb + 8 <= rend; eb += 8) {
        int s0 = g_csr[eb + g];
        int s1 = g_csr[eb + 4 + g];
        uint4 v0 = h4[s0 * 8 + c];
        uint4 v1 = h4[s1 * 8 + c];
        const __half2* hp0 = (const __half2*)&v0;
        const __half2* hp1 = (const __half2*)&v1;
        #pragma unroll
        for (int j = 0; j < 4; j++) {
            float2 f0 = __half22float2(hp0[j]);
            float2 f1 = __half22float2(hp1[j]);
            acc[2 * j]     += f0.x + f1.x;
            acc[2 * j + 1] += f0.y + f1.y;
        }
    }
    for (; eb < rend; eb += 4) {
        int e = eb + g;
        if (e < rend) {
            int s = g_csr[e];
            uint4 v = h4[s * 8 + c];
            const __half2* hp = (const __half2*)&v;
            #pragma unroll
            for (int j = 0; j < 4; j++) {
                float2 f = __half22float2(hp[j]);
                acc[2 * j]     += f.x;
                acc[2 * j + 1] += f.y;
            }
        }
    }
    #pragma unroll
    for (int j = 0; j < 8; j++) {
        acc[j] += __shfl_xor_sync(0xffffffffu, acc[j], 8);
        acc[j] += __shfl_xor_sync(0xffffffffu, acc[j], 16);
    }
    {   // self term (h1' already dinv-scaled)
        uint4 v = h4[node * 8 + c];
        const __half2* hp = (const __half2*)&v;
        #pragma unroll
        for (int j = 0; j < 4; j++) {
            float2 f = __half22float2(hp[j]);
            acc[2 * j]     += f.x;
            acc[2 * j + 1] += f.y;
        }
    }

    float di = g_dinv[node];
    float4 bb0 = ((const float4*)b1)[c * 2];
    float4 bb1 = ((const float4*)b1)[c * 2 + 1];
    float4 wv0 = ((const float4*)g_w)[c * 2];
    float4 wv1 = ((const float4*)g_w)[c * 2 + 1];
    float bb[8] = {bb0.x, bb0.y, bb0.z, bb0.w, bb1.x, bb1.y, bb1.z, bb1.w};
    float wv[8] = {wv0.x, wv0.y, wv0.z, wv0.w, wv1.x, wv1.y, wv1.z, wv1.w};

    float p = 0.f;
    #pragma unroll
    for (int j = 0; j < 8; j++) {
        float a = fmaxf(fmaf(di, acc[j], bb[j]), 0.f);
        p = fmaf(a, wv[j], p);
    }
    p += __shfl_xor_sync(0xffffffffu, p, 1);
    p += __shfl_xor_sync(0xffffffffu, p, 2);
    p += __shfl_xor_sync(0xffffffffu, p, 4);
    if (lane == 0) g_z[node] = di * p;           // z' = dinv * (a1 . w)
}

// ---------------- agg2 (scalar): out[d] = dinv_d*(sum_s z'[s] + z'[d]) + cb ----------------
__global__ void agg2_kernel(float* __restrict__ out) {
    int warp = threadIdx.x >> 5, lane = threadIdx.x & 31;
    int node = blockIdx.x * 8 + warp;
    if (node >= N_NODES) return;

    int rbeg = g_rowptr[node];
    int rend = g_rowptr[node + 1];
    float acc = 0.f;
    for (int e = rbeg + lane; e < rend; e += 32) {
        acc += g_z[g_csr[e]];
    }
    #pragma unroll
    for (int o = 16; o > 0; o >>= 1) acc += __shfl_xor_sync(0xffffffffu, acc, o);
    if (lane == 0) out[node] = g_dinv[node] * (acc + g_z[node]) + g_cb;
}

// ---------------- launch: fork-only experiment (gemm1 || scatter) ----------------
extern "C" void kernel_launch(void* const* d_in, const int* in_sizes, int n_in,
                              void* d_out, int out_size) {
    const float* x  = (const float*)d_in[0];
    const void*  ei = d_in[1];                 // int32 or int64, probed on device
    const float* W1 = (const float*)d_in[2];
    const float* b1 = (const float*)d_in[3];
    const float* W2 = (const float*)d_in[4];
    const float* b2 = (const float*)d_in[5];
    const float* Wc = (const float*)d_in[6];
    const float* bc = (const float*)d_in[7];
    float* out = (float*)d_out;

    cudaStream_t s2 = 0;
    cudaEvent_t evF = 0, evJ = 0;
    bool forked = (cudaStreamCreateWithFlags(&s2, cudaStreamNonBlocking) == cudaSuccess);
    if (forked) forked = (cudaEventCreateWithFlags(&evF, cudaEventDisableTiming) == cudaSuccess);
    if (forked) forked = (cudaEventCreateWithFlags(&evJ, cudaEventDisableTiming) == cudaSuccess);

    prep_kernel   <<<PREP_NB + 2, 256>>>((const unsigned*)ei, W2, b2, Wc, bc);
    hist_kernel   <<<N_EDGES / 256, 256>>>(ei);
    scan1_kernel  <<<SCAN_NB, SCAN_B>>>();
    scan2_kernel  <<<1, 256>>>();
    scan3_kernel  <<<(N_NODES + 511) / 512, 512>>>();

    if (forked) {
        cudaEventRecord(evF, 0);
        cudaStreamWaitEvent(s2, evF, 0);
        gemm1_kernel<<<(N_NODES + 63) / 64, 256, 0, s2>>>(x, W1);   // branch A (tensor)
        scatter_kernel<<<N_EDGES / 256, 256>>>(ei);                 // branch B (atomics)
        cudaEventRecord(evJ, s2);
        cudaStreamWaitEvent(0, evJ, 0);                             // join
    } else {
        scatter_kernel<<<N_EDGES / 256, 256>>>(ei);
        gemm1_kernel  <<<(N_NODES + 63) / 64, 256>>>(x, W1);
    }

    agg1_kernel   <<<(N_NODES + 7) / 8, 256>>>(b1);
    agg2_kernel   <<<(N_NODES + 7) / 8, 256>>>(out);
    // stream/event objects intentionally not destroyed: destroying objects that
    // participate in an active capture is illegal; host-side leak is bounded
    // (kernel_launch runs only for correctness + capture), device memory untouched.
}

// round 13
// speedup vs baseline: 1.1171x; 1.0102x over previous
#include <cuda_runtime.h>
#include <cuda_fp16.h>

#define N_NODES 100000
#define N_EDGES 3200000
#define IN_DIM  128
#define HID     64

#define SCAN_B  512
#define SCAN_NB ((N_NODES + SCAN_B - 1) / SCAN_B)   // 196
#define PREP_NB ((N_NODES + 255) / 256)             // 391

// ---------------- scratch (device globals; no allocation allowed) ----------------
__device__ int     g_is64;                  // 1 if edge_index is int64, 0 if int32
__device__ int     g_deg[N_NODES];
__device__ float   g_dinv[N_NODES];
__device__ int     g_rowptr[N_NODES + 1];
__device__ int     g_cursor[N_NODES];
__device__ int     g_scan[N_NODES];
__device__ int     g_bsum[SCAN_NB];
__device__ int     g_csr[N_EDGES];          // src index only
__device__ __half2 g_h1h[N_NODES * (HID/2)];// h1' = dinv * (x @ W1^T), fp16
__device__ float   g_z[N_NODES];            // z'  = dinv * (a1 . w)
__device__ float   g_w[HID];                // w = W2^T @ Wc
__device__ float   g_cb;                    // b2.Wc + bc

// ---------------- prep: deg init + dtype probe + classifier fold (one launch) ----------------
__global__ void prep_kernel(const unsigned* __restrict__ ei32,
                            const float* __restrict__ W2, const float* __restrict__ b2,
                            const float* __restrict__ Wc, const float* __restrict__ bc) {
    int b = blockIdx.x, tid = threadIdx.x;
    if (b < PREP_NB) {
        int i = b * 256 + tid;
        if (i < N_NODES) g_deg[i] = 1;          // self-loop counts as 1
    } else if (b == PREP_NB) {
        if (tid == 0) {
            // int64 ids in [0,100000) => every odd 32-bit word is 0.
            unsigned o = 0;
            #pragma unroll
            for (int i = 1; i < 128; i += 2) o |= ei32[i];
            g_is64 = (o == 0) ? 1 : 0;
        }
    } else {
        if (tid < HID) {
            float s = 0.f;
            #pragma unroll
            for (int j = 0; j < HID; j++) s = fmaf(Wc[j], W2[j * HID + tid], s);
            g_w[tid] = s;
            if (tid == 0) {
                float c = bc[0];
                #pragma unroll
                for (int j = 0; j < HID; j++) c = fmaf(b2[j], Wc[j], c);
                g_cb = c;
            }
        }
    }
}

__device__ __forceinline__ int edge_at(const void* ei, long long idx) {
    if (g_is64) return (int)((const long long*)ei)[idx];
    return ((const int*)ei)[idx];
}

// ---------------- dst-degree histogram (1 edge/thread: max atomic MLP) ----------------
__global__ void hist_kernel(const void* __restrict__ ei) {
    int e = blockIdx.x * blockDim.x + threadIdx.x;
    if (e < N_EDGES) {
        int d = edge_at(ei, (long long)N_EDGES + e);
        atomicAdd(&g_deg[d], 1);
    }
}

// ---------------- 2-phase exclusive scan of (deg-1) ----------------
__global__ void scan1_kernel() {
    __shared__ int wsum[16];
    const int tid  = threadIdx.x;
    const int lane = tid & 31, warp = tid >> 5;
    const int i = blockIdx.x * SCAN_B + tid;
    int v = (i < N_NODES) ? (g_deg[i] - 1) : 0;
    int s = v;
    #pragma unroll
    for (int o = 1; o < 32; o <<= 1) {
        int t = __shfl_up_sync(0xffffffffu, s, o);
        if (lane >= o) s += t;
    }
    if (lane == 31) wsum[warp] = s;
    __syncthreads();
    if (warp == 0) {
        int ws = (lane < 16) ? wsum[lane] : 0;
        #pragma unroll
        for (int o = 1; o < 16; o <<= 1) {
            int t = __shfl_up_sync(0xffffffffu, ws, o);
            if (lane >= o) ws += t;
        }
        if (lane < 16) wsum[lane] = ws;
    }
    __syncthreads();
    int excl = s - v + (warp ? wsum[warp - 1] : 0);
    if (i < N_NODES) g_scan[i] = excl;
    if (tid == SCAN_B - 1) g_bsum[blockIdx.x] = excl + v;   // block total
}

// scan3: each block derives its own offset by reducing bsum[j < bid] (<=196
// L2-resident ints, warp 0 only) — replaces the former single-block scan2.
__global__ void scan3_kernel() {
    __shared__ int s_boff;
    const int tid = threadIdx.x, bid = blockIdx.x;
    if (tid < 32) {
        int sum = 0;
        for (int j = tid; j < bid; j += 32) sum += g_bsum[j];
        #pragma unroll
        for (int o = 16; o > 0; o >>= 1) sum += __shfl_xor_sync(0xffffffffu, sum, o);
        if (tid == 0) s_boff = sum;
    }
    __syncthreads();
    int i = bid * SCAN_B + tid;
    if (i < N_NODES) {
        int off = g_scan[i] + s_boff;
        g_rowptr[i] = off;
        g_cursor[i] = off;
        g_dinv[i]   = rsqrtf((float)g_deg[i]);
    }
    if (i == 0) g_rowptr[N_NODES] = N_EDGES;   // sum(deg-1) == E
}

// ---------------- counting-sort scatter (1 edge/thread: max atomic MLP) ----------------
__global__ void scatter_kernel(const void* __restrict__ ei) {
    int e = blockIdx.x * blockDim.x + threadIdx.x;
    if (e < N_EDGES) {
        int s = edge_at(ei, e);
        int d = edge_at(ei, (long long)N_EDGES + e);
        int pos = atomicAdd(&g_cursor[d], 1);
        g_csr[pos] = s;
    }
}

// ---------------- tf32 helpers ----------------
__device__ __forceinline__ unsigned f2tf(float f) {
    unsigned u;
    asm("cvt.rna.tf32.f32 %0, %1;" : "=r"(u) : "f"(f));
    return u;
}

__device__ __forceinline__ void mma_tf32(float* c,
                                         unsigned a0, unsigned a1, unsigned a2, unsigned a3,
                                         unsigned b0, unsigned b1) {
    asm volatile(
        "mma.sync.aligned.m16n8k8.row.col.f32.tf32.tf32.f32 "
        "{%0,%1,%2,%3},{%4,%5,%6,%7},{%8,%9},{%0,%1,%2,%3};"
        : "+f"(c[0]), "+f"(c[1]), "+f"(c[2]), "+f"(c[3])
        : "r"(a0), "r"(a1), "r"(a2), "r"(a3), "r"(b0), "r"(b1));
}

// ---------------- GEMM1 (tensor core, tf32): h1' = fp16(dinv * (x @ W1^T)) ----------------
#define GPAD 68
__global__ void gemm1_kernel(const float* __restrict__ X, const float* __restrict__ W) {
    __shared__ unsigned As[64 * GPAD];   // A tile (tf32 bits), [node_local][k]
    __shared__ unsigned Ws[64 * GPAD];   // W tile (tf32 bits), [out_ch][k]

    const int tid  = threadIdx.x;
    const int warp = tid >> 5, lane = tid & 31;
    const int g    = lane >> 2, tig = lane & 3;
    const int m0   = (warp >> 1) * 16;
    const int nb   = (warp & 1) * 32;
    const int node0 = blockIdx.x * 64;

    float c[4][4];
    #pragma unroll
    for (int nt = 0; nt < 4; nt++)
        #pragma unroll
        for (int j = 0; j < 4; j++) c[nt][j] = 0.f;

    #pragma unroll
    for (int kt = 0; kt < IN_DIM; kt += 64) {
        #pragma unroll
        for (int i = tid; i < 64 * 64; i += 256) {
            int r = i >> 6, k = i & 63;
            int node = node0 + r;
            if (node > N_NODES - 1) node = N_NODES - 1;
            As[r * GPAD + k] = f2tf(X[node * IN_DIM + kt + k]);
        }
        #pragma unroll
        for (int i = tid; i < 64 * 64; i += 256) {
            int r = i >> 6, k = i & 63;
            Ws[r * GPAD + k] = f2tf(W[r * IN_DIM + kt + k]);
        }
        __syncthreads();

        #pragma unroll
        for (int ks = 0; ks < 8; ks++) {
            int k0 = ks * 8;
            unsigned a0 = As[(m0 + g)     * GPAD + k0 + tig];
            unsigned a1 = As[(m0 + g + 8) * GPAD + k0 + tig];
            unsigned a2 = As[(m0 + g)     * GPAD + k0 + tig + 4];
            unsigned a3 = As[(m0 + g + 8) * GPAD + k0 + tig + 4];
            #pragma unroll
            for (int nt = 0; nt < 4; nt++) {
                int n0 = nb + nt * 8;
                unsigned b0 = Ws[(n0 + g) * GPAD + k0 + tig];
                unsigned b1 = Ws[(n0 + g) * GPAD + k0 + tig + 4];
                mma_tf32(c[nt], a0, a1, a2, a3, b0, b1);
            }
        }
        __syncthreads();
    }

    int nodeA = node0 + m0 + g;
    int nodeB = nodeA + 8;
    int colh  = (nb >> 1) + tig;
    if (nodeA < N_NODES) {
        float di = g_dinv[nodeA];
        #pragma unroll
        for (int nt = 0; nt < 4; nt++)
            g_h1h[nodeA * 32 + colh + nt * 4] = __floats2half2_rn(c[nt][0] * di, c[nt][1] * di);
    }
    if (nodeB < N_NODES) {
        float di = g_dinv[nodeB];
        #pragma unroll
        for (int nt = 0; nt < 4; nt++)
            g_h1h[nodeB * 32 + colh + nt * 4] = __floats2half2_rn(c[nt][2] * di, c[nt][3] * di);
    }
}

// ---------------- agg1: 8 edges per iteration (2 gathers in flight), fused fold ----------------
__global__ void agg1_kernel(const float* __restrict__ b1) {
    int warp = threadIdx.x >> 5, lane = threadIdx.x & 31;
    int node = blockIdx.x * 8 + warp;
    if (node >= N_NODES) return;

    const int g = lane >> 3, c = lane & 7;
    const uint4* __restrict__ h4 = (const uint4*)g_h1h;   // 8 channels per uint4

    int rbeg = g_rowptr[node];
    int rend = g_rowptr[node + 1];

    float acc[8];
    #pragma unroll
    for (int j = 0; j < 8; j++) acc[j] = 0.f;

    int eb = rbeg;
    for (; eb + 8 <= rend; eb += 8) {
        int s0 = g_csr[eb + g];
        int s1 = g_csr[eb + 4 + g];
        uint4 v0 = h4[s0 * 8 + c];
        uint4 v1 = h4[s1 * 8 + c];
        const __half2* hp0 = (const __half2*)&v0;
        const __half2* hp1 = (const __half2*)&v1;
        #pragma unroll
        for (int j = 0; j < 4; j++) {
            float2 f0 = __half22float2(hp0[j]);
            float2 f1 = __half22float2(hp1[j]);
            acc[2 * j]     += f0.x + f1.x;
            acc[2 * j + 1] += f0.y + f1.y;
        }
    }
    for (; eb < rend; eb += 4) {
        int e = eb + g;
        if (e < rend) {
            int s = g_csr[e];
            uint4 v = h4[s * 8 + c];
            const __half2* hp = (const __half2*)&v;
            #pragma unroll
            for (int j = 0; j < 4; j++) {
                float2 f = __half22float2(hp[j]);
                acc[2 * j]     += f.x;
                acc[2 * j + 1] += f.y;
            }
        }
    }
    #pragma unroll
    for (int j = 0; j < 8; j++) {
        acc[j] += __shfl_xor_sync(0xffffffffu, acc[j], 8);
        acc[j] += __shfl_xor_sync(0xffffffffu, acc[j], 16);
    }
    {   // self term (h1' already dinv-scaled)
        uint4 v = h4[node * 8 + c];
        const __half2* hp = (const __half2*)&v;
        #pragma unroll
        for (int j = 0; j < 4; j++) {
            float2 f = __half22float2(hp[j]);
            acc[2 * j]     += f.x;
            acc[2 * j + 1] += f.y;
        }
    }

    float di = g_dinv[node];
    float4 bb0 = ((const float4*)b1)[c * 2];
    float4 bb1 = ((const float4*)b1)[c * 2 + 1];
    float4 wv0 = ((const float4*)g_w)[c * 2];
    float4 wv1 = ((const float4*)g_w)[c * 2 + 1];
    float bb[8] = {bb0.x, bb0.y, bb0.z, bb0.w, bb1.x, bb1.y, bb1.z, bb1.w};
    float wv[8] = {wv0.x, wv0.y, wv0.z, wv0.w, wv1.x, wv1.y, wv1.z, wv1.w};

    float p = 0.f;
    #pragma unroll
    for (int j = 0; j < 8; j++) {
        float a = fmaxf(fmaf(di, acc[j], bb[j]), 0.f);
        p = fmaf(a, wv[j], p);
    }
    p += __shfl_xor_sync(0xffffffffu, p, 1);
    p += __shfl_xor_sync(0xffffffffu, p, 2);
    p += __shfl_xor_sync(0xffffffffu, p, 4);
    if (lane == 0) g_z[node] = di * p;           // z' = dinv * (a1 . w)
}

// ---------------- agg2 (scalar): out[d] = dinv_d*(sum_s z'[s] + z'[d]) + cb ----------------
__global__ void agg2_kernel(float* __restrict__ out) {
    int warp = threadIdx.x >> 5, lane = threadIdx.x & 31;
    int node = blockIdx.x * 8 + warp;
    if (node >= N_NODES) return;

    int rbeg = g_rowptr[node];
    int rend = g_rowptr[node + 1];
    float acc = 0.f;
    for (int e = rbeg + lane; e < rend; e += 32) {
        acc += g_z[g_csr[e]];
    }
    #pragma unroll
    for (int o = 16; o > 0; o >>= 1) acc += __shfl_xor_sync(0xffffffffu, acc, o);
    if (lane == 0) out[node] = g_dinv[node] * (acc + g_z[node]) + g_cb;
}

// ---------------- launch: fork gemm1 || scatter (proven win, R12) ----------------
extern "C" void kernel_launch(void* const* d_in, const int* in_sizes, int n_in,
                              void* d_out, int out_size) {
    const float* x  = (const float*)d_in[0];
    const void*  ei = d_in[1];                 // int32 or int64, probed on device
    const float* W1 = (const float*)d_in[2];
    const float* b1 = (const float*)d_in[3];
    const float* W2 = (const float*)d_in[4];
    const float* b2 = (const float*)d_in[5];
    const float* Wc = (const float*)d_in[6];
    const float* bc = (const float*)d_in[7];
    float* out = (float*)d_out;

    cudaStream_t s2 = 0;
    cudaEvent_t evF = 0, evJ = 0;
    bool forked = (cudaStreamCreateWithFlags(&s2, cudaStreamNonBlocking) == cudaSuccess);
    if (forked) forked = (cudaEventCreateWithFlags(&evF, cudaEventDisableTiming) == cudaSuccess);
    if (forked) forked = (cudaEventCreateWithFlags(&evJ, cudaEventDisableTiming) == cudaSuccess);

    prep_kernel   <<<PREP_NB + 2, 256>>>((const unsigned*)ei, W2, b2, Wc, bc);
    hist_kernel   <<<N_EDGES / 256, 256>>>(ei);
    scan1_kernel  <<<SCAN_NB, SCAN_B>>>();
    scan3_kernel  <<<SCAN_NB, SCAN_B>>>();

    if (forked) {
        cudaEventRecord(evF, 0);
        cudaStreamWaitEvent(s2, evF, 0);
        gemm1_kernel<<<(N_NODES + 63) / 64, 256, 0, s2>>>(x, W1);   // branch A (tensor)
        scatter_kernel<<<N_EDGES / 256, 256>>>(ei);                 // branch B (atomics)
        cudaEventRecord(evJ, s2);
        cudaStreamWaitEvent(0, evJ, 0);                             // join
    } else {
        scatter_kernel<<<N_EDGES / 256, 256>>>(ei);
        gemm1_kernel  <<<(N_NODES + 63) / 64, 256>>>(x, W1);
    }

    agg1_kernel   <<<(N_NODES + 7) / 8, 256>>>(b1);
    agg2_kernel   <<<(N_NODES + 7) / 8, 256>>>(out);
    // stream/event objects intentionally not destroyed: destroying objects that
    // participate in an active capture is illegal; host-side leak is bounded
    // (kernel_launch runs only for correctness + capture), device memory untouched.
}

// round 14
// speedup vs baseline: 1.1190x; 1.0017x over previous
#include <cuda_runtime.h>
#include <cuda_fp16.h>

#define N_NODES 100000
#define N_EDGES 3200000
#define IN_DIM  128
#define HID     64

#define SCAN_B  512
#define SCAN_NB ((N_NODES + SCAN_B - 1) / SCAN_B)   // 196
#define PREP_NB ((N_NODES + 255) / 256)             // 391

// ---------------- scratch (device globals; no allocation allowed) ----------------
__device__ int     g_is64;                  // 1 if edge_index is int64, 0 if int32
__device__ int     g_deg[N_NODES];
__device__ float   g_dinv[N_NODES];
__device__ int     g_rowptr[N_NODES + 1];
__device__ int     g_cursor[N_NODES];
__device__ int     g_scan[N_NODES];
__device__ int     g_bsum[SCAN_NB];
__device__ int     g_csr[N_EDGES];          // src index only
__device__ __half2 g_h1h[N_NODES * (HID/2)];// h1 (unscaled, then *= dinv), fp16
__device__ float   g_z[N_NODES];            // z'  = dinv * (a1 . w)
__device__ float   g_w[HID];                // w = W2^T @ Wc
__device__ float   g_cb;                    // b2.Wc + bc

// ---------------- prep: deg init + dtype probe + classifier fold (one launch) ----------------
__global__ void prep_kernel(const unsigned* __restrict__ ei32,
                            const float* __restrict__ W2, const float* __restrict__ b2,
                            const float* __restrict__ Wc, const float* __restrict__ bc) {
    int b = blockIdx.x, tid = threadIdx.x;
    if (b < PREP_NB) {
        int i = b * 256 + tid;
        if (i < N_NODES) g_deg[i] = 1;          // self-loop counts as 1
    } else if (b == PREP_NB) {
        if (tid == 0) {
            // int64 ids in [0,100000) => every odd 32-bit word is 0.
            unsigned o = 0;
            #pragma unroll
            for (int i = 1; i < 128; i += 2) o |= ei32[i];
            g_is64 = (o == 0) ? 1 : 0;
        }
    } else {
        if (tid < HID) {
            float s = 0.f;
            #pragma unroll
            for (int j = 0; j < HID; j++) s = fmaf(Wc[j], W2[j * HID + tid], s);
            g_w[tid] = s;
            if (tid == 0) {
                float c = bc[0];
                #pragma unroll
                for (int j = 0; j < HID; j++) c = fmaf(b2[j], Wc[j], c);
                g_cb = c;
            }
        }
    }
}

__device__ __forceinline__ int edge_at(const void* ei, long long idx) {
    if (g_is64) return (int)((const long long*)ei)[idx];
    return ((const int*)ei)[idx];
}

// ---------------- dst-degree histogram (1 edge/thread: max atomic MLP) ----------------
__global__ void hist_kernel(const void* __restrict__ ei) {
    int e = blockIdx.x * blockDim.x + threadIdx.x;
    if (e < N_EDGES) {
        int d = edge_at(ei, (long long)N_EDGES + e);
        atomicAdd(&g_deg[d], 1);
    }
}

// ---------------- 2-phase exclusive scan of (deg-1) ----------------
__global__ void scan1_kernel() {
    __shared__ int wsum[16];
    const int tid  = threadIdx.x;
    const int lane = tid & 31, warp = tid >> 5;
    const int i = blockIdx.x * SCAN_B + tid;
    int v = (i < N_NODES) ? (g_deg[i] - 1) : 0;
    int s = v;
    #pragma unroll
    for (int o = 1; o < 32; o <<= 1) {
        int t = __shfl_up_sync(0xffffffffu, s, o);
        if (lane >= o) s += t;
    }
    if (lane == 31) wsum[warp] = s;
    __syncthreads();
    if (warp == 0) {
        int ws = (lane < 16) ? wsum[lane] : 0;
        #pragma unroll
        for (int o = 1; o < 16; o <<= 1) {
            int t = __shfl_up_sync(0xffffffffu, ws, o);
            if (lane >= o) ws += t;
        }
        if (lane < 16) wsum[lane] = ws;
    }
    __syncthreads();
    int excl = s - v + (warp ? wsum[warp - 1] : 0);
    if (i < N_NODES) g_scan[i] = excl;
    if (tid == SCAN_B - 1) g_bsum[blockIdx.x] = excl + v;   // block total
}

// scan3: each block derives its own offset by reducing bsum[j < bid]
__global__ void scan3_kernel() {
    __shared__ int s_boff;
    const int tid = threadIdx.x, bid = blockIdx.x;
    if (tid < 32) {
        int sum = 0;
        for (int j = tid; j < bid; j += 32) sum += g_bsum[j];
        #pragma unroll
        for (int o = 16; o > 0; o >>= 1) sum += __shfl_xor_sync(0xffffffffu, sum, o);
        if (tid == 0) s_boff = sum;
    }
    __syncthreads();
    int i = bid * SCAN_B + tid;
    if (i < N_NODES) {
        int off = g_scan[i] + s_boff;
        g_rowptr[i] = off;
        g_cursor[i] = off;
        g_dinv[i]   = rsqrtf((float)g_deg[i]);
    }
    if (i == 0) g_rowptr[N_NODES] = N_EDGES;   // sum(deg-1) == E
}

// ---------------- counting-sort scatter (1 edge/thread: max atomic MLP) ----------------
__global__ void scatter_kernel(const void* __restrict__ ei) {
    int e = blockIdx.x * blockDim.x + threadIdx.x;
    if (e < N_EDGES) {
        int s = edge_at(ei, e);
        int d = edge_at(ei, (long long)N_EDGES + e);
        int pos = atomicAdd(&g_cursor[d], 1);
        g_csr[pos] = s;
    }
}

// ---------------- tf32 helpers ----------------
__device__ __forceinline__ unsigned f2tf(float f) {
    unsigned u;
    asm("cvt.rna.tf32.f32 %0, %1;" : "=r"(u) : "f"(f));
    return u;
}

__device__ __forceinline__ void mma_tf32(float* c,
                                         unsigned a0, unsigned a1, unsigned a2, unsigned a3,
                                         unsigned b0, unsigned b1) {
    asm volatile(
        "mma.sync.aligned.m16n8k8.row.col.f32.tf32.tf32.f32 "
        "{%0,%1,%2,%3},{%4,%5,%6,%7},{%8,%9},{%0,%1,%2,%3};"
        : "+f"(c[0]), "+f"(c[1]), "+f"(c[2]), "+f"(c[3])
        : "r"(a0), "r"(a1), "r"(a2), "r"(a3), "r"(b0), "r"(b1));
}

// ---------------- GEMM1 (tensor core, tf32): h1 = fp16(x @ W1^T), UNSCALED ----------------
// (dinv not known yet: gemm1 runs in parallel with the CSR build chain)
#define GPAD 68
__global__ void gemm1_kernel(const float* __restrict__ X, const float* __restrict__ W) {
    __shared__ unsigned As[64 * GPAD];   // A tile (tf32 bits), [node_local][k]
    __shared__ unsigned Ws[64 * GPAD];   // W tile (tf32 bits), [out_ch][k]

    const int tid  = threadIdx.x;
    const int warp = tid >> 5, lane = tid & 31;
    const int g    = lane >> 2, tig = lane & 3;
    const int m0   = (warp >> 1) * 16;
    const int nb   = (warp & 1) * 32;
    const int node0 = blockIdx.x * 64;

    float c[4][4];
    #pragma unroll
    for (int nt = 0; nt < 4; nt++)
        #pragma unroll
        for (int j = 0; j < 4; j++) c[nt][j] = 0.f;

    #pragma unroll
    for (int kt = 0; kt < IN_DIM; kt += 64) {
        #pragma unroll
        for (int i = tid; i < 64 * 64; i += 256) {
            int r = i >> 6, k = i & 63;
            int node = node0 + r;
            if (node > N_NODES - 1) node = N_NODES - 1;
            As[r * GPAD + k] = f2tf(X[node * IN_DIM + kt + k]);
        }
        #pragma unroll
        for (int i = tid; i < 64 * 64; i += 256) {
            int r = i >> 6, k = i & 63;
            Ws[r * GPAD + k] = f2tf(W[r * IN_DIM + kt + k]);
        }
        __syncthreads();

        #pragma unroll
        for (int ks = 0; ks < 8; ks++) {
            int k0 = ks * 8;
            unsigned a0 = As[(m0 + g)     * GPAD + k0 + tig];
            unsigned a1 = As[(m0 + g + 8) * GPAD + k0 + tig];
            unsigned a2 = As[(m0 + g)     * GPAD + k0 + tig + 4];
            unsigned a3 = As[(m0 + g + 8) * GPAD + k0 + tig + 4];
            #pragma unroll
            for (int nt = 0; nt < 4; nt++) {
                int n0 = nb + nt * 8;
                unsigned b0 = Ws[(n0 + g) * GPAD + k0 + tig];
                unsigned b1 = Ws[(n0 + g) * GPAD + k0 + tig + 4];
                mma_tf32(c[nt], a0, a1, a2, a3, b0, b1);
            }
        }
        __syncthreads();
    }

    int nodeA = node0 + m0 + g;
    int nodeB = nodeA + 8;
    int colh  = (nb >> 1) + tig;
    if (nodeA < N_NODES) {
        #pragma unroll
        for (int nt = 0; nt < 4; nt++)
            g_h1h[nodeA * 32 + colh + nt * 4] = __floats2half2_rn(c[nt][0], c[nt][1]);
    }
    if (nodeB < N_NODES) {
        #pragma unroll
        for (int nt = 0; nt < 4; nt++)
            g_h1h[nodeB * 32 + colh + nt * 4] = __floats2half2_rn(c[nt][2], c[nt][3]);
    }
}

// ---------------- scale: h1 *= dinv[node] (runs in fork alongside scatter) ----------------
__global__ void scale_kernel() {
    int idx = blockIdx.x * 256 + threadIdx.x;        // uint4 index: N_NODES*8 total
    if (idx >= N_NODES * 8) return;
    float di = g_dinv[idx >> 3];
    uint4 v = ((uint4*)g_h1h)[idx];
    __half2* hp = (__half2*)&v;
    #pragma unroll
    for (int j = 0; j < 4; j++) {
        float2 f = __half22float2(hp[j]);
        hp[j] = __floats2half2_rn(f.x * di, f.y * di);
    }
    ((uint4*)g_h1h)[idx] = v;
}

// ---------------- agg1: 8 edges per iteration (2 gathers in flight), fused fold ----------------
__global__ void agg1_kernel(const float* __restrict__ b1) {
    int warp = threadIdx.x >> 5, lane = threadIdx.x & 31;
    int node = blockIdx.x * 8 + warp;
    if (node >= N_NODES) return;

    const int g = lane >> 3, c = lane & 7;
    const uint4* __restrict__ h4 = (const uint4*)g_h1h;   // 8 channels per uint4

    int rbeg = g_rowptr[node];
    int rend = g_rowptr[node + 1];

    float acc[8];
    #pragma unroll
    for (int j = 0; j < 8; j++) acc[j] = 0.f;

    int eb = rbeg;
    for (; eb + 8 <= rend; eb += 8) {
        int s0 = g_csr[eb + g];
        int s1 = g_csr[eb + 4 + g];
        uint4 v0 = h4[s0 * 8 + c];
        uint4 v1 = h4[s1 * 8 + c];
        const __half2* hp0 = (const __half2*)&v0;
        const __half2* hp1 = (const __half2*)&v1;
        #pragma unroll
        for (int j = 0; j < 4; j++) {
            float2 f0 = __half22float2(hp0[j]);
            float2 f1 = __half22float2(hp1[j]);
            acc[2 * j]     += f0.x + f1.x;
            acc[2 * j + 1] += f0.y + f1.y;
        }
    }
    for (; eb < rend; eb += 4) {
        int e = eb + g;
        if (e < rend) {
            int s = g_csr[e];
            uint4 v = h4[s * 8 + c];
            const __half2* hp = (const __half2*)&v;
            #pragma unroll
            for (int j = 0; j < 4; j++) {
                float2 f = __half22float2(hp[j]);
                acc[2 * j]     += f.x;
                acc[2 * j + 1] += f.y;
            }
        }
    }
    #pragma unroll
    for (int j = 0; j < 8; j++) {
        acc[j] += __shfl_xor_sync(0xffffffffu, acc[j], 8);
        acc[j] += __shfl_xor_sync(0xffffffffu, acc[j], 16);
    }
    {   // self term (h1 already dinv-scaled by scale_kernel)
        uint4 v = h4[node * 8 + c];
        const __half2* hp = (const __half2*)&v;
        #pragma unroll
        for (int j = 0; j < 4; j++) {
            float2 f = __half22float2(hp[j]);
            acc[2 * j]     += f.x;
            acc[2 * j + 1] += f.y;
        }
    }

    float di = g_dinv[node];
    float4 bb0 = ((const float4*)b1)[c * 2];
    float4 bb1 = ((const float4*)b1)[c * 2 + 1];
    float4 wv0 = ((const float4*)g_w)[c * 2];
    float4 wv1 = ((const float4*)g_w)[c * 2 + 1];
    float bb[8] = {bb0.x, bb0.y, bb0.z, bb0.w, bb1.x, bb1.y, bb1.z, bb1.w};
    float wv[8] = {wv0.x, wv0.y, wv0.z, wv0.w, wv1.x, wv1.y, wv1.z, wv1.w};

    float p = 0.f;
    #pragma unroll
    for (int j = 0; j < 8; j++) {
        float a = fmaxf(fmaf(di, acc[j], bb[j]), 0.f);
        p = fmaf(a, wv[j], p);
    }
    p += __shfl_xor_sync(0xffffffffu, p, 1);
    p += __shfl_xor_sync(0xffffffffu, p, 2);
    p += __shfl_xor_sync(0xffffffffu, p, 4);
    if (lane == 0) g_z[node] = di * p;           // z' = dinv * (a1 . w)
}

// ---------------- agg2 (scalar): out[d] = dinv_d*(sum_s z'[s] + z'[d]) + cb ----------------
__global__ void agg2_kernel(float* __restrict__ out) {
    int warp = threadIdx.x >> 5, lane = threadIdx.x & 31;
    int node = blockIdx.x * 8 + warp;
    if (node >= N_NODES) return;

    int rbeg = g_rowptr[node];
    int rend = g_rowptr[node + 1];
    float acc = 0.f;
    for (int e = rbeg + lane; e < rend; e += 32) {
        acc += g_z[g_csr[e]];
    }
    #pragma unroll
    for (int o = 16; o > 0; o >>= 1) acc += __shfl_xor_sync(0xffffffffu, acc, o);
    if (lane == 0) out[node] = g_dinv[node] * (acc + g_z[node]) + g_cb;
}

// ---------------- launch: gemm1 || (prep..scan3), then scale || scatter ----------------
extern "C" void kernel_launch(void* const* d_in, const int* in_sizes, int n_in,
                              void* d_out, int out_size) {
    const float* x  = (const float*)d_in[0];
    const void*  ei = d_in[1];                 // int32 or int64, probed on device
    const float* W1 = (const float*)d_in[2];
    const float* b1 = (const float*)d_in[3];
    const float* W2 = (const float*)d_in[4];
    const float* b2 = (const float*)d_in[5];
    const float* Wc = (const float*)d_in[6];
    const float* bc = (const float*)d_in[7];
    float* out = (float*)d_out;

    cudaStream_t s2 = 0;
    cudaEvent_t evF1 = 0, evF2 = 0, evJ = 0;
    bool forked = (cudaStreamCreateWithFlags(&s2, cudaStreamNonBlocking) == cudaSuccess);
    if (forked) forked = (cudaEventCreateWithFlags(&evF1, cudaEventDisableTiming) == cudaSuccess);
    if (forked) forked = (cudaEventCreateWithFlags(&evF2, cudaEventDisableTiming) == cudaSuccess);
    if (forked) forked = (cudaEventCreateWithFlags(&evJ,  cudaEventDisableTiming) == cudaSuccess);

    if (forked) {
        // fork 1 at t=0: gemm1 (tensor) runs under the CSR-build chain (atomics/scan)
        cudaEventRecord(evF1, 0);
        cudaStreamWaitEvent(s2, evF1, 0);
        gemm1_kernel<<<(N_NODES + 63) / 64, 256, 0, s2>>>(x, W1);

        prep_kernel <<<PREP_NB + 2, 256>>>((const unsigned*)ei, W2, b2, Wc, bc);
        hist_kernel <<<N_EDGES / 256, 256>>>(ei);
        scan1_kernel<<<SCAN_NB, SCAN_B>>>();
        scan3_kernel<<<SCAN_NB, SCAN_B>>>();

        // fork 2: scale (needs gemm1 [s2] + scan3 [main]) under scatter (main)
        cudaEventRecord(evF2, 0);
        cudaStreamWaitEvent(s2, evF2, 0);          // s2: gemm1 done, now also past scan3
        scale_kernel<<<(N_NODES * 8 + 255) / 256, 256, 0, s2>>>();
        scatter_kernel<<<N_EDGES / 256, 256>>>(ei);
        cudaEventRecord(evJ, s2);
        cudaStreamWaitEvent(0, evJ, 0);            // join
    } else {
        prep_kernel <<<PREP_NB + 2, 256>>>((const unsigned*)ei, W2, b2, Wc, bc);
        hist_kernel <<<N_EDGES / 256, 256>>>(ei);
        scan1_kernel<<<SCAN_NB, SCAN_B>>>();
        scan3_kernel<<<SCAN_NB, SCAN_B>>>();
        gemm1_kernel<<<(N_NODES + 63) / 64, 256>>>(x, W1);
        scale_kernel<<<(N_NODES * 8 + 255) / 256, 256>>>();
        scatter_kernel<<<N_EDGES / 256, 256>>>(ei);
    }

    agg1_kernel<<<(N_NODES + 7) / 8, 256>>>(b1);
    agg2_kernel<<<(N_NODES + 7) / 8, 256>>>(out);
    // stream/event objects intentionally not destroyed: destroying objects that
    // participate in an active capture is illegal; host-side leak is bounded
    // (kernel_launch runs only for correctness + capture), device memory untouched.
}